// round 9
// baseline (speedup 1.0000x reference)
#include <cuda_runtime.h>
#include <cstdint>

// Custom_Pooling_3D: 2x2 sum-of-squares pooling + sqrt.
// Input  per batch: x[i*512 + j*16 + c], i,j in [0,32), c in [0,16)  (16384 f32)
// Output per batch: y[oi*256 + oj*16 + c], oi,oj in [0,16)           (4096  f32)
// y = sqrt( sum_{di,dj in {0,1}} x[2oi+di, 2oj+dj, c]^2 )
//
// Converged (R1-R8): traffic is irreducible (64 MB read, each element used
// exactly once, + 16 MB coalesced write = 80 MB, all through LTS). This
// configuration (256-thread blocks, 4096 blocks, one float4/thread, 24 regs,
// plain vectorized accesses) times at 10.69 us = 7.48 TB/s effective = the
// path-independent LTS cap. Verified non-levers: L2 policy hints (evict_last,
// .cs), 256-bit accesses, per-thread load batching, persistent/reduced grids,
// 512-thread blocks — each neutral or regressed. This is the floor kernel.

#define BATCH     1024
#define IN_PER_B  16384
#define OUT_PER_B 4096
#define TOTAL_V4  (BATCH * OUT_PER_B / 4)   // 1,048,576 float4 outputs

__device__ __forceinline__ float fsqrt_approx(float v) {
    float r;
    asm("sqrt.approx.f32 %0, %1;" : "=f"(r) : "f"(v));
    return r;
}

__global__ __launch_bounds__(256)
void pool3d_kernel(const float* __restrict__ x, float* __restrict__ out) {
    int idx = blockIdx.x * blockDim.x + threadIdx.x;   // float4 output index
    if (idx >= TOTAL_V4) return;

    // Decompose: idx = b*1024 + oi*64 + oj*4 + c4
    int b   = idx >> 10;
    int r   = idx & 1023;
    int oi  = r >> 6;
    int rr  = r & 63;
    int oj  = rr >> 2;
    int c4  = rr & 3;

    // Input float4 base within batch: (2*oi)*512 + (2*oj)*16 + c4*4 floats
    //  -> /4 = 256*oi + 8*oj + c4 (float4 units)
    const float4* __restrict__ xin =
        reinterpret_cast<const float4*>(x) + (size_t)b * (IN_PER_B / 4);
    int base = (oi << 8) + (oj << 3) + c4;

    float4 a0 = xin[base];          // (2oi,   2oj)
    float4 a1 = xin[base + 4];      // (2oi,   2oj+1)  (+16 floats)
    float4 a2 = xin[base + 128];    // (2oi+1, 2oj)    (+512 floats)
    float4 a3 = xin[base + 132];    // (2oi+1, 2oj+1)

    float4 y;
    y.x = fsqrt_approx(a0.x*a0.x + a1.x*a1.x + a2.x*a2.x + a3.x*a3.x);
    y.y = fsqrt_approx(a0.y*a0.y + a1.y*a1.y + a2.y*a2.y + a3.y*a3.y);
    y.z = fsqrt_approx(a0.z*a0.z + a1.z*a1.z + a2.z*a2.z + a3.z*a3.z);
    y.w = fsqrt_approx(a0.w*a0.w + a1.w*a1.w + a2.w*a2.w + a3.w*a3.w);

    reinterpret_cast<float4*>(out)[idx] = y;
}

extern "C" void kernel_launch(void* const* d_in, const int* in_sizes, int n_in,
                              void* d_out, int out_size) {
    const float* x = (const float*)d_in[0];   // input_state [1024, 16384]
    // d_in[1] is T — structural 0/1 pooling matrix, not needed at runtime.
    float* out = (float*)d_out;               // [1024, 4096]

    const int threads = 256;
    const int blocks = (TOTAL_V4 + threads - 1) / threads;  // 4096
    pool3d_kernel<<<blocks, threads>>>(x, out);
}

// round 10
// speedup vs baseline: 1.0269x; 1.0269x over previous
#include <cuda_runtime.h>
#include <cstdint>

// Custom_Pooling_3D: 2x2 sum-of-squares pooling + sqrt.
// Input  per batch: x[i*512 + j*16 + c], i,j in [0,32), c in [0,16)  (16384 f32)
// Output per batch: y[oi*256 + oj*16 + c], oi,oj in [0,16)           (4096  f32)
// y = sqrt( sum_{di,dj in {0,1}} x[2oi+di, 2oj+dj, c]^2 )
//
// Converged (R1-R9): traffic is irreducible (64 MB read, each element used
// exactly once, + 16 MB coalesced write = 80 MB, all through LTS). This
// configuration (256-thread blocks, 4096 blocks, one float4/thread, 24 regs,
// plain vectorized accesses) times at ~10.7 us = ~7.5 TB/s effective = the
// path-independent LTS cap. Verified non-levers: L2 policy hints (evict_last,
// .cs), 256-bit accesses, per-thread load batching, persistent/reduced grids,
// 512-thread blocks — each neutral or regressed 15-18%. This is the floor.

#define BATCH     1024
#define IN_PER_B  16384
#define OUT_PER_B 4096
#define TOTAL_V4  (BATCH * OUT_PER_B / 4)   // 1,048,576 float4 outputs

__device__ __forceinline__ float fsqrt_approx(float v) {
    float r;
    asm("sqrt.approx.f32 %0, %1;" : "=f"(r) : "f"(v));
    return r;
}

__global__ __launch_bounds__(256)
void pool3d_kernel(const float* __restrict__ x, float* __restrict__ out) {
    int idx = blockIdx.x * blockDim.x + threadIdx.x;   // float4 output index
    if (idx >= TOTAL_V4) return;

    // Decompose: idx = b*1024 + oi*64 + oj*4 + c4
    int b   = idx >> 10;
    int r   = idx & 1023;
    int oi  = r >> 6;
    int rr  = r & 63;
    int oj  = rr >> 2;
    int c4  = rr & 3;

    // Input float4 base within batch: (2*oi)*512 + (2*oj)*16 + c4*4 floats
    //  -> /4 = 256*oi + 8*oj + c4 (float4 units)
    const float4* __restrict__ xin =
        reinterpret_cast<const float4*>(x) + (size_t)b * (IN_PER_B / 4);
    int base = (oi << 8) + (oj << 3) + c4;

    float4 a0 = xin[base];          // (2oi,   2oj)
    float4 a1 = xin[base + 4];      // (2oi,   2oj+1)  (+16 floats)
    float4 a2 = xin[base + 128];    // (2oi+1, 2oj)    (+512 floats)
    float4 a3 = xin[base + 132];    // (2oi+1, 2oj+1)

    float4 y;
    y.x = fsqrt_approx(a0.x*a0.x + a1.x*a1.x + a2.x*a2.x + a3.x*a3.x);
    y.y = fsqrt_approx(a0.y*a0.y + a1.y*a1.y + a2.y*a2.y + a3.y*a3.y);
    y.z = fsqrt_approx(a0.z*a0.z + a1.z*a1.z + a2.z*a2.z + a3.z*a3.z);
    y.w = fsqrt_approx(a0.w*a0.w + a1.w*a1.w + a2.w*a2.w + a3.w*a3.w);

    reinterpret_cast<float4*>(out)[idx] = y;
}

extern "C" void kernel_launch(void* const* d_in, const int* in_sizes, int n_in,
                              void* d_out, int out_size) {
    const float* x = (const float*)d_in[0];   // input_state [1024, 16384]
    // d_in[1] is T — structural 0/1 pooling matrix, not needed at runtime.
    float* out = (float*)d_out;               // [1024, 4096]

    const int threads = 256;
    const int blocks = (TOTAL_V4 + threads - 1) / threads;  // 4096
    pool3d_kernel<<<blocks, threads>>>(x, out);
}